// round 2
// baseline (speedup 1.0000x reference)
#include <cuda_runtime.h>
#include <math.h>

// Problem constants (fixed shapes for this problem instance)
#define NMAX 50000
#define EMAX 800000
#define C_IN 64
#define C_HID 64
#define C_OUT 40

// Scratch (allocation-free rule: __device__ globals). 16B-aligned for v4 ops.
__device__ __align__(16) float g_h1[NMAX * C_HID];    // x @ W1
__device__ __align__(16) float g_agg1[NMAX * C_HID];  // aggregated -> relu'd (in place)
__device__ __align__(16) float g_h2[NMAX * C_OUT];    // feat @ W2
__device__ __align__(16) float g_agg2[NMAX * C_OUT];  // aggregated layer 2
__device__ int   g_deg[NMAX];
__device__ float g_dinv[NMAX];

__device__ __forceinline__ void red_add_v4(float* p, float4 v) {
    asm volatile("red.global.add.v4.f32 [%0], {%1,%2,%3,%4};"
                 :: "l"(p), "f"(v.x), "f"(v.y), "f"(v.z), "f"(v.w)
                 : "memory");
}

// ---------------------------------------------------------------------------
// Zero scratch accumulators + degree counters (one grid-stride pass)
// ---------------------------------------------------------------------------
__global__ void zero_kernel(int N) {
    int total = N * C_HID;  // largest buffer
    for (int i = blockIdx.x * blockDim.x + threadIdx.x; i < total;
         i += gridDim.x * blockDim.x) {
        g_agg1[i] = 0.f;
        if (i < N * C_OUT) g_agg2[i] = 0.f;
        if (i < N)         g_deg[i]  = 0;
    }
}

// ---------------------------------------------------------------------------
// Degree of destination nodes (unit weights); self-loop (+1) added in dinv
// ---------------------------------------------------------------------------
__global__ void deg_kernel(const int* __restrict__ ei, int E) {
    int e = blockIdx.x * blockDim.x + threadIdx.x;
    if (e < E) {
        int d = ei[E + e];  // edge_index[1][e]
        atomicAdd(&g_deg[d], 1);
    }
}

__global__ void dinv_kernel(int N) {
    int i = blockIdx.x * blockDim.x + threadIdx.x;
    if (i < N) g_dinv[i] = rsqrtf((float)(g_deg[i] + 1));  // +1 self loop
}

// ---------------------------------------------------------------------------
// Dense GEMM: H[N,COUT] = X[N,CIN] @ W[CIN,COUT]
// W cached in smem; 64-row X tiles in smem. LAYER1 reads param X -> g_h1,
// else reads g_agg1 (post-relu features) -> g_h2.
// ---------------------------------------------------------------------------
template <int CIN, int COUT, bool LAYER1>
__global__ void gemm_kernel(const float* __restrict__ X,
                            const float* __restrict__ W, int N) {
    constexpr int ROWS = 64;
    __shared__ float Ws[CIN * COUT];
    __shared__ float Xs[ROWS * CIN];

    const float* Xin = LAYER1 ? X : g_agg1;
    float* H = LAYER1 ? g_h1 : g_h2;

    int tid  = threadIdx.y * COUT + threadIdx.x;
    int nthr = blockDim.x * blockDim.y;

    for (int i = tid; i < CIN * COUT; i += nthr) Ws[i] = W[i];

    int row0  = blockIdx.x * ROWS;
    int nrows = min(ROWS, N - row0);
    for (int i = tid; i < nrows * CIN; i += nthr) Xs[i] = Xin[row0 * CIN + i];
    __syncthreads();

    int c = threadIdx.x;
    for (int r = threadIdx.y; r < nrows; r += blockDim.y) {
        float acc = 0.f;
#pragma unroll
        for (int k = 0; k < CIN; k++) acc += Xs[r * CIN + k] * Ws[k * COUT + c];
        H[(size_t)(row0 + r) * COUT + c] = acc;
    }
}

// ---------------------------------------------------------------------------
// Edge scatter: agg[dst] += h[src] * dinv[src]*dinv[dst]
// One thread per (edge, float4 chunk). red.global.add.v4.f32 (no return).
// ---------------------------------------------------------------------------
template <int C, bool LAYER1>
__global__ void scatter_kernel(const int* __restrict__ ei, int E) {
    constexpr int CH = C / 4;
    long long t = (long long)blockIdx.x * blockDim.x + threadIdx.x;
    if (t >= (long long)E * CH) return;
    int e  = (int)(t / CH);
    int ch = (int)(t % CH);

    int s = ei[e];
    int d = ei[E + e];
    float norm = g_dinv[s] * g_dinv[d];

    const float* h = LAYER1 ? g_h1 : g_h2;
    float* agg     = LAYER1 ? g_agg1 : g_agg2;

    float4 v = *(const float4*)(h + (size_t)s * C + ch * 4);
    v.x *= norm; v.y *= norm; v.z *= norm; v.w *= norm;
    red_add_v4(agg + (size_t)d * C + ch * 4, v);
}

// ---------------------------------------------------------------------------
// Layer-1 epilogue: feat = relu(agg1 + h1*dinv^2 + b1)   (in place on agg1)
// ---------------------------------------------------------------------------
__global__ void combine_relu_kernel(const float* __restrict__ b1, int N) {
    int i = blockIdx.x * blockDim.x + threadIdx.x;
    if (i >= N * C_HID) return;
    int n = i / C_HID;
    int c = i - n * C_HID;
    float di = g_dinv[n];
    float v  = g_agg1[i] + g_h1[i] * di * di + b1[c];
    g_agg1[i] = fmaxf(v, 0.f);
}

// ---------------------------------------------------------------------------
// Layer-2 epilogue fused with log_softmax. One warp per node row (C_OUT=40:
// lane handles c=lane and, for lane<8, c=lane+32).
// ---------------------------------------------------------------------------
__global__ void final_kernel(const float* __restrict__ b2,
                             float* __restrict__ out, int N) {
    int gwarp = (blockIdx.x * blockDim.x + threadIdx.x) >> 5;
    int lane  = threadIdx.x & 31;
    if (gwarp >= N) return;

    float di = g_dinv[gwarp];
    float d2 = di * di;
    size_t base = (size_t)gwarp * C_OUT;

    float v0 = g_agg2[base + lane] + g_h2[base + lane] * d2 + b2[lane];
    float v1 = -INFINITY;
    bool has2 = lane < (C_OUT - 32);
    if (has2)
        v1 = g_agg2[base + lane + 32] + g_h2[base + lane + 32] * d2 + b2[lane + 32];

    float m = fmaxf(v0, v1);
#pragma unroll
    for (int o = 16; o; o >>= 1) m = fmaxf(m, __shfl_xor_sync(0xFFFFFFFFu, m, o));

    float s = expf(v0 - m) + (has2 ? expf(v1 - m) : 0.f);
#pragma unroll
    for (int o = 16; o; o >>= 1) s += __shfl_xor_sync(0xFFFFFFFFu, s, o);

    float lg = m + logf(s);
    out[base + lane] = v0 - lg;
    if (has2) out[base + lane + 32] = v1 - lg;
}

// ---------------------------------------------------------------------------
// Launch
// ---------------------------------------------------------------------------
extern "C" void kernel_launch(void* const* d_in, const int* in_sizes, int n_in,
                              void* d_out, int out_size) {
    const float* x  = (const float*)d_in[0];
    const int*   ei = (const int*)d_in[1];   // int32: JAX default x64-disabled
    const float* W1 = (const float*)d_in[2];
    const float* b1 = (const float*)d_in[3];
    const float* W2 = (const float*)d_in[4];
    const float* b2 = (const float*)d_in[5];
    float* out = (float*)d_out;

    int N = in_sizes[0] / C_IN;
    int E = in_sizes[1] / 2;

    // Zero accumulators + degree
    zero_kernel<<<1024, 256>>>(N);

    // Degree / normalization
    deg_kernel<<<(E + 255) / 256, 256>>>(ei, E);
    dinv_kernel<<<(N + 255) / 256, 256>>>(N);

    // Layer 1: h1 = x @ W1
    gemm_kernel<C_IN, C_HID, true><<<(N + 63) / 64, dim3(C_HID, 4)>>>(x, W1, N);

    // Scatter edges into agg1
    {
        long long tot = (long long)E * (C_HID / 4);
        scatter_kernel<C_HID, true><<<(unsigned)((tot + 255) / 256), 256>>>(ei, E);
    }

    // agg1 = relu(agg1 + h1*dinv^2 + b1)
    combine_relu_kernel<<<(N * C_HID + 255) / 256, 256>>>(b1, N);

    // Layer 2: h2 = feat @ W2
    gemm_kernel<C_HID, C_OUT, false><<<(N + 63) / 64, dim3(C_OUT, 6)>>>(nullptr, W2, N);

    // Scatter edges into agg2
    {
        long long tot = (long long)E * (C_OUT / 4);
        scatter_kernel<C_OUT, false><<<(unsigned)((tot + 255) / 256), 256>>>(ei, E);
    }

    // Epilogue + log_softmax
    final_kernel<<<(N + 7) / 8, 256>>>(b2, out, N);
}